// round 9
// baseline (speedup 1.0000x reference)
#include <cuda_runtime.h>
#include <cstdint>

// PointOnSurfaceLoss: B=8, M=512, N=8192
// inputs: keypoint [B,3,M] f32, pc [B,3,N] f32, sn [B,3,N] f32
// output: loss [B,M,1,1] f32  (B*M = 4096 floats)
//
// Warp-autonomous fused kernel: 512 blocks = 128 keypoint-groups x 4 N-splits,
// 8 warps/block, each warp owns 256 points and broadcasts them to its 32
// keypoint-lanes via coalesced LDG.128 (no smem, no __syncthreads).
// Publish: per-lane atomicMax(~packed_key); 32nd-arriving warp per group
// finalizes (outlined epilogue) and resets state for graph replay.

#define BATCH 8
#define MM    512
#define NN    8192
#define NSPLIT 4
#define TN    (NN / NSPLIT)      // 2048 points per split
#define WPB   8                  // warps per block
#define PW    (TN / 2 / WPB)     // 128 pairs per warp (256 points)
#define NGRP  (BATCH * MM / 32)  // 128 keypoint groups
#define NARRIVE (NSPLIT * WPB)   // 32 warp arrivals per group
#define EPSV  1e-7f

// zero-initialized device state; reset to zero by the finalizing warp each launch
__device__ unsigned long long g_inv[NGRP * 32];   // ~key, max-reduced
__device__ unsigned int       g_cnt[NGRP];        // warp-arrival counters

union f2u  { float2 f; uint64_t u; };
union f4u2 { float4 f; ulonglong2 u; };   // .u.x = (f.x,f.y), .u.y = (f.z,f.w)

__device__ __forceinline__ uint64_t add2(uint64_t a, uint64_t b) {
    uint64_t r; asm("add.rn.f32x2 %0, %1, %2;" : "=l"(r) : "l"(a), "l"(b)); return r;
}
__device__ __forceinline__ uint64_t mul2(uint64_t a, uint64_t b) {
    uint64_t r; asm("mul.rn.f32x2 %0, %1, %2;" : "=l"(r) : "l"(a), "l"(b)); return r;
}
__device__ __forceinline__ uint64_t fma2(uint64_t a, uint64_t b, uint64_t c) {
    uint64_t r; asm("fma.rn.f32x2 %0, %1, %2, %3;" : "=l"(r) : "l"(a), "l"(b), "l"(c)); return r;
}
__device__ __forceinline__ uint64_t pack2(float lo, float hi) {
    uint64_t r; asm("mov.b64 %0, {%1, %2};" : "=l"(r) : "f"(lo), "f"(hi)); return r;
}

// evaluate one pair given packed x/y/z coordinate pairs
#define EVAL_PAIR(XP, YP, ZP, T, DOUT, COUT)                               \
    do {                                                                   \
        const uint64_t dx_ = add2((XP), nkx2);                             \
        const uint64_t dy_ = add2((YP), nky2);                             \
        const uint64_t dz_ = add2((ZP), nkz2);                             \
        uint64_t s_ = mul2(dx_, dx_);                                      \
        s_ = fma2(dy_, dy_, s_);                                           \
        s_ = fma2(dz_, dz_, s_);                                           \
        f2u d2_; d2_.u = s_;                                               \
        if (d2_.f.y < d2_.f.x) { DOUT = d2_.f.y; COUT = 2 * (T) + 1; }     \
        else                   { DOUT = d2_.f.x; COUT = 2 * (T);     }     \
    } while (0)

// Cold path: runs once per group by the last-arriving warp.
__device__ __noinline__ void finalize_group(const float* __restrict__ keypoint,
                                            const float* __restrict__ pc,
                                            const float* __restrict__ sn,
                                            float* __restrict__ out,
                                            int grp, int lane)
{
    const int b = grp >> 4;
    const int m = (grp & 15) * 32 + lane;

    __threadfence();
    // atomic read (RMW at L2) of the fully-reduced key, then decode
    const unsigned long long inv = atomicMax(&g_inv[grp * 32 + lane], 0ULL);
    const int bn = (int)((~inv) & 0xFFFFFFFFu);

    const float* kpb = keypoint + (size_t)b * 3 * MM;
    const float kx = kpb[0 * MM + m];
    const float ky = kpb[1 * MM + m];
    const float kz = kpb[2 * MM + m];

    const float* pcb = pc + (size_t)b * 3 * NN;
    const float* snb = sn + (size_t)b * 3 * NN;
    const float px = pcb[0 * NN + bn];
    const float py = pcb[1 * NN + bn];
    const float pz = pcb[2 * NN + bn];
    const float sx = snb[0 * NN + bn];
    const float sy = snb[1 * NN + bn];
    const float sz = snb[2 * NN + bn];

    const float dx = kx - px;
    const float dy = ky - py;
    const float dz = kz - pz;
    const float nrm = sqrtf(dx * dx + dy * dy + dz * dz);
    const float dot = (sx * dx + sy * dy + sz * dz) / (nrm + EPSV);
    out[b * MM + m] = dot * dot;

    // reset for next graph replay (deterministic)
    atomicExch(&g_inv[grp * 32 + lane], 0ULL);
    if (lane == 0) atomicExch(&g_cnt[grp], 0u);
}

__global__ __launch_bounds__(256, 4)
void pos_loss_fused(const float* __restrict__ keypoint,
                    const float* __restrict__ pc,
                    const float* __restrict__ sn,
                    float* __restrict__ out)
{
    const int blk  = blockIdx.x;             // 512
    const int grp  = blk >> 2;               // keypoint group 0..127
    const int spl  = blk & 3;                // N split
    const int b    = grp >> 4;
    const int tid  = threadIdx.x;
    const int wid  = tid >> 5;
    const int lane = tid & 31;
    const int m    = (grp & 15) * 32 + lane;

    uint64_t nkx2, nky2, nkz2;
    {
        const float* kpb = keypoint + (size_t)b * 3 * MM;
        const float kx = kpb[0 * MM + m];
        const float ky = kpb[1 * MM + m];
        const float kz = kpb[2 * MM + m];
        nkx2 = pack2(-kx, -kx);
        nky2 = pack2(-ky, -ky);
        nkz2 = pack2(-kz, -kz);
    }

    const float* pcb = pc + (size_t)b * 3 * NN;
    const int nwarp = spl * TN + wid * (PW * 2);   // first point of this warp's slice

    // all lanes read the SAME addresses -> coalesced broadcast LDG.128 (L2 hits)
    const float4* xg = (const float4*)(pcb + 0 * NN + nwarp);
    const float4* yg = (const float4*)(pcb + 1 * NN + nwarp);
    const float4* zg = (const float4*)(pcb + 2 * NN + nwarp);

    float best  = 3.4e38f;
    int   bcode = 0;                         // 2*t + bit, t in 0..PW-1

    #pragma unroll 4
    for (int it = 0; it < PW / 4; ++it) {    // 4 pairs (8 points) per iteration
        f4u2 xA, xB, yA, yB, zA, zB;
        xA.f = xg[2 * it + 0];               // x of pairs 4it, 4it+1
        xB.f = xg[2 * it + 1];               // x of pairs 4it+2, 4it+3
        yA.f = yg[2 * it + 0];
        yB.f = yg[2 * it + 1];
        zA.f = zg[2 * it + 0];
        zB.f = zg[2 * it + 1];

        const int t0 = it * 4;
        float d0, d1, d2, d3; int c0, c1, c2, c3;
        EVAL_PAIR(xA.u.x, yA.u.x, zA.u.x, t0 + 0, d0, c0);
        EVAL_PAIR(xA.u.y, yA.u.y, zA.u.y, t0 + 1, d1, c1);
        EVAL_PAIR(xB.u.x, yB.u.x, zB.u.x, t0 + 2, d2, c2);
        EVAL_PAIR(xB.u.y, yB.u.y, zB.u.y, t0 + 3, d3, c3);

        // tournament tree (strict < keeps lower t on ties)
        float d01, d23; int c01, c23;
        if (d1 < d0) { d01 = d1; c01 = c1; } else { d01 = d0; c01 = c0; }
        if (d3 < d2) { d23 = d3; c23 = c3; } else { d23 = d2; c23 = c2; }
        float dT; int cT;
        if (d23 < d01) { dT = d23; cT = c23; } else { dT = d01; cT = c01; }
        if (dT < best) { best = dT; bcode = cT; }
    }

    // packed key: (bits(d2) << 32) | n  — uint64 min == lexicographic (d, n) min
    {
        const int n = nwarp + bcode;         // global point index within batch
        uint32_t dbits; asm("mov.b32 %0, %1;" : "=r"(dbits) : "f"(best));
        const unsigned long long key =
            ((unsigned long long)dbits << 32) | (unsigned)n;
        atomicMax(&g_inv[grp * 32 + lane], ~key);
    }
    __threadfence();

    // warp arrival; the 32nd warp for this group finalizes
    unsigned int prev = 0;
    if (lane == 0) prev = atomicAdd(&g_cnt[grp], 1u);
    prev = __shfl_sync(0xFFFFFFFFu, prev, 0);

    if (prev == NARRIVE - 1u) {
        finalize_group(keypoint, pc, sn, out, grp, lane);
    }
}

extern "C" void kernel_launch(void* const* d_in, const int* in_sizes, int n_in,
                              void* d_out, int out_size)
{
    const float* keypoint = (const float*)d_in[0]; // 8*3*512
    const float* pc       = (const float*)d_in[1]; // 8*3*8192
    const float* sn       = (const float*)d_in[2]; // 8*3*8192
    float* out            = (float*)d_out;         // 4096

    pos_loss_fused<<<NGRP * NSPLIT, 256>>>(keypoint, pc, sn, out);  // 512 blocks
}

// round 11
// speedup vs baseline: 1.0429x; 1.0429x over previous
#include <cuda_runtime.h>
#include <cstdint>

// PointOnSurfaceLoss: B=8, M=512, N=8192
// inputs: keypoint [B,3,M] f32, pc [B,3,N] f32, sn [B,3,N] f32
// output: loss [B,M,1,1] f32  (B*M = 4096 floats)
//
// Fused single kernel, 512 blocks = 128 keypoint-groups x 4 N-splits.
// Block stages its 2048-point tile in smem (one barrier); each warp owns
// 256 points (16 groups of 16), broadcast-LDS to its 32 keypoint-lanes.
// Inner loop: FMNMX tree over 16 distances per group + one scalar compare;
// exact index recovered post-loop by bit-identical recompute of the winning
// group (descending scan -> first occurrence). Publish via per-lane
// atomicMax(~((d2bits<<32)|n)); 32nd-arriving warp finalizes + resets.

#define BATCH 8
#define MM    512
#define NN    8192
#define NSPLIT 4
#define TN    (NN / NSPLIT)      // 2048 points per split-tile
#define WPB   8                  // warps per block
#define PPW   256                // points per warp
#define NGROUPS 16               // 16-point groups per warp
#define NGRP  (BATCH * MM / 32)  // 128 keypoint groups
#define NARRIVE (NSPLIT * WPB)   // 32 warp arrivals per group
#define EPSV  1e-7f

// zero-initialized device state; reset by the finalizing warp each launch
__device__ unsigned long long g_inv[NGRP * 32];   // ~key, max-reduced
__device__ unsigned int       g_cnt[NGRP];        // warp-arrival counters

union f2u  { float2 f; uint64_t u; };
union f4u2 { float4 f; ulonglong2 u; };   // .u.x = (f.x,f.y), .u.y = (f.z,f.w)

__device__ __forceinline__ uint64_t add2(uint64_t a, uint64_t b) {
    uint64_t r; asm("add.rn.f32x2 %0, %1, %2;" : "=l"(r) : "l"(a), "l"(b)); return r;
}
__device__ __forceinline__ uint64_t mul2(uint64_t a, uint64_t b) {
    uint64_t r; asm("mul.rn.f32x2 %0, %1, %2;" : "=l"(r) : "l"(a), "l"(b)); return r;
}
__device__ __forceinline__ uint64_t fma2(uint64_t a, uint64_t b, uint64_t c) {
    uint64_t r; asm("fma.rn.f32x2 %0, %1, %2, %3;" : "=l"(r) : "l"(a), "l"(b), "l"(c)); return r;
}
__device__ __forceinline__ uint64_t pack2(float lo, float hi) {
    uint64_t r; asm("mov.b64 %0, {%1, %2};" : "=l"(r) : "f"(lo), "f"(hi)); return r;
}

// squared distance for a packed point-pair; bit-exact chain (reused in recovery)
__device__ __forceinline__ float2 eval_pair(uint64_t xp, uint64_t yp, uint64_t zp,
                                            uint64_t nkx2, uint64_t nky2, uint64_t nkz2)
{
    const uint64_t dx = add2(xp, nkx2);
    const uint64_t dy = add2(yp, nky2);
    const uint64_t dz = add2(zp, nkz2);
    uint64_t s = mul2(dx, dx);
    s = fma2(dy, dy, s);
    s = fma2(dz, dz, s);
    f2u r; r.u = s;
    return r.f;
}

// Cold path: runs once per group by the last-arriving warp.
__device__ __noinline__ void finalize_group(const float* __restrict__ keypoint,
                                            const float* __restrict__ pc,
                                            const float* __restrict__ sn,
                                            float* __restrict__ out,
                                            int grp, int lane)
{
    const int b = grp >> 4;
    const int m = (grp & 15) * 32 + lane;

    __threadfence();
    const unsigned long long inv = atomicMax(&g_inv[grp * 32 + lane], 0ULL);
    const int bn = (int)((~inv) & 0xFFFFFFFFu);

    const float* kpb = keypoint + (size_t)b * 3 * MM;
    const float kx = kpb[0 * MM + m];
    const float ky = kpb[1 * MM + m];
    const float kz = kpb[2 * MM + m];

    const float* pcb = pc + (size_t)b * 3 * NN;
    const float* snb = sn + (size_t)b * 3 * NN;
    const float px = pcb[0 * NN + bn];
    const float py = pcb[1 * NN + bn];
    const float pz = pcb[2 * NN + bn];
    const float sx = snb[0 * NN + bn];
    const float sy = snb[1 * NN + bn];
    const float sz = snb[2 * NN + bn];

    const float dx = kx - px;
    const float dy = ky - py;
    const float dz = kz - pz;
    const float nrm = sqrtf(dx * dx + dy * dy + dz * dz);
    const float dot = (sx * dx + sy * dy + sz * dz) / (nrm + EPSV);
    out[b * MM + m] = dot * dot;

    // reset for next graph replay (deterministic)
    atomicExch(&g_inv[grp * 32 + lane], 0ULL);
    if (lane == 0) atomicExch(&g_cnt[grp], 0u);
}

__global__ __launch_bounds__(256, 4)
void pos_loss_fused(const float* __restrict__ keypoint,
                    const float* __restrict__ pc,
                    const float* __restrict__ sn,
                    float* __restrict__ out)
{
    __shared__ float4 xs4[TN / 4];   // 8 KB each: SoA tile rows, float4-aligned
    __shared__ float4 ys4[TN / 4];
    __shared__ float4 zs4[TN / 4];

    const int blk  = blockIdx.x;             // 512
    const int grp  = blk >> 2;               // keypoint group 0..127
    const int spl  = blk & 3;                // N split
    const int b    = grp >> 4;
    const int tid  = threadIdx.x;
    const int wid  = tid >> 5;
    const int lane = tid & 31;
    const int m    = (grp & 15) * 32 + lane;

    uint64_t nkx2, nky2, nkz2;
    {
        const float* kpb = keypoint + (size_t)b * 3 * MM;
        const float kx = kpb[0 * MM + m];
        const float ky = kpb[1 * MM + m];
        const float kz = kpb[2 * MM + m];
        nkx2 = pack2(-kx, -kx);
        nky2 = pack2(-ky, -ky);
        nkz2 = pack2(-kz, -kz);
    }

    const float* pcb = pc + (size_t)b * 3 * NN;
    const int n0 = spl * TN;

    // stage tile (L2 hits), float4 copies
    {
        const float4* gx = (const float4*)(pcb + 0 * NN + n0);
        const float4* gy = (const float4*)(pcb + 1 * NN + n0);
        const float4* gz = (const float4*)(pcb + 2 * NN + n0);
        #pragma unroll
        for (int i = tid; i < TN / 4; i += 256) {
            xs4[i] = gx[i];
            ys4[i] = gy[i];
            zs4[i] = gz[i];
        }
    }
    __syncthreads();

    // this warp's slice: 256 points = 64 float4, broadcast reads
    const float4* xw = xs4 + wid * (PPW / 4);
    const float4* yw = ys4 + wid * (PPW / 4);
    const float4* zw = zs4 + wid * (PPW / 4);

    float bestd = 3.4e38f;
    int   bestg = 0;

    #pragma unroll 2
    for (int g = 0; g < NGROUPS; ++g) {      // 16 points per group
        const int q = g * 4;
        f4u2 x0, x1, x2, x3, y0, y1, y2, y3, z0, z1, z2, z3;
        x0.f = xw[q + 0]; x1.f = xw[q + 1]; x2.f = xw[q + 2]; x3.f = xw[q + 3];
        y0.f = yw[q + 0]; y1.f = yw[q + 1]; y2.f = yw[q + 2]; y3.f = yw[q + 3];
        z0.f = zw[q + 0]; z1.f = zw[q + 1]; z2.f = zw[q + 2]; z3.f = zw[q + 3];

        const float2 dA = eval_pair(x0.u.x, y0.u.x, z0.u.x, nkx2, nky2, nkz2);
        const float2 dB = eval_pair(x0.u.y, y0.u.y, z0.u.y, nkx2, nky2, nkz2);
        const float2 dC = eval_pair(x1.u.x, y1.u.x, z1.u.x, nkx2, nky2, nkz2);
        const float2 dD = eval_pair(x1.u.y, y1.u.y, z1.u.y, nkx2, nky2, nkz2);
        const float2 dE = eval_pair(x2.u.x, y2.u.x, z2.u.x, nkx2, nky2, nkz2);
        const float2 dF = eval_pair(x2.u.y, y2.u.y, z2.u.y, nkx2, nky2, nkz2);
        const float2 dG = eval_pair(x3.u.x, y3.u.x, z3.u.x, nkx2, nky2, nkz2);
        const float2 dH = eval_pair(x3.u.y, y3.u.y, z3.u.y, nkx2, nky2, nkz2);

        // pure FMNMX tree: 15 mins, no predicates
        const float mA = fminf(dA.x, dA.y);
        const float mB = fminf(dB.x, dB.y);
        const float mC = fminf(dC.x, dC.y);
        const float mD = fminf(dD.x, dD.y);
        const float mE = fminf(dE.x, dE.y);
        const float mF = fminf(dF.x, dF.y);
        const float mG = fminf(dG.x, dG.y);
        const float mH = fminf(dH.x, dH.y);
        const float mAB = fminf(mA, mB);
        const float mCD = fminf(mC, mD);
        const float mEF = fminf(mE, mF);
        const float mGH = fminf(mG, mH);
        const float mg  = fminf(fminf(mAB, mCD), fminf(mEF, mGH));

        // strict < keeps the earliest group on ties (first occurrence)
        if (mg < bestd) { bestd = mg; bestg = g; }
    }

    // index recovery: recompute the winning group (bit-identical chain),
    // descending scan so the LOWEST matching index wins
    int bcode = 0;   // 0..15 within group
    {
        const int q = bestg * 4;
        #pragma unroll
        for (int j = 3; j >= 0; --j) {
            f4u2 xv, yv, zv;
            xv.f = xw[q + j]; yv.f = yw[q + j]; zv.f = zw[q + j];
            const float2 dHi = eval_pair(xv.u.y, yv.u.y, zv.u.y, nkx2, nky2, nkz2);
            const float2 dLo = eval_pair(xv.u.x, yv.u.x, zv.u.x, nkx2, nky2, nkz2);
            if (dHi.y == bestd) bcode = 4 * j + 3;
            if (dHi.x == bestd) bcode = 4 * j + 2;
            if (dLo.y == bestd) bcode = 4 * j + 1;
            if (dLo.x == bestd) bcode = 4 * j + 0;
        }
    }

    // packed key: (bits(d2) << 32) | n — uint64 min == lexicographic (d, n) min
    {
        const int n = n0 + wid * PPW + bestg * 16 + bcode;
        uint32_t dbits; asm("mov.b32 %0, %1;" : "=r"(dbits) : "f"(bestd));
        const unsigned long long key =
            ((unsigned long long)dbits << 32) | (unsigned)n;
        atomicMax(&g_inv[grp * 32 + lane], ~key);
    }
    __threadfence();

    // warp arrival; 32nd warp for this keypoint-group finalizes
    unsigned int prev = 0;
    if (lane == 0) prev = atomicAdd(&g_cnt[grp], 1u);
    prev = __shfl_sync(0xFFFFFFFFu, prev, 0);

    if (prev == NARRIVE - 1u) {
        finalize_group(keypoint, pc, sn, out, grp, lane);
    }
}

extern "C" void kernel_launch(void* const* d_in, const int* in_sizes, int n_in,
                              void* d_out, int out_size)
{
    const float* keypoint = (const float*)d_in[0]; // 8*3*512
    const float* pc       = (const float*)d_in[1]; // 8*3*8192
    const float* sn       = (const float*)d_in[2]; // 8*3*8192
    float* out            = (float*)d_out;         // 4096

    pos_loss_fused<<<NGRP * NSPLIT, 256>>>(keypoint, pc, sn, out);  // 512 blocks
}

// round 14
// speedup vs baseline: 1.2424x; 1.1913x over previous
#include <cuda_runtime.h>
#include <cstdint>

// PointOnSurfaceLoss: B=8, M=512, N=8192
// inputs: keypoint [B,3,M] f32, pc [B,3,N] f32, sn [B,3,N] f32
// output: loss [B,M,1,1] f32  (B*M = 4096 floats)
//
// Fused single kernel, 512 blocks = 128 keypoint-groups x 4 N-splits.
// Block stages its 2048-point tile in smem (one barrier); each warp owns
// 256 points (32 groups of 8), broadcast-LDS to its 32 keypoint-lanes.
// Inner loop: FMNMX tree over 8 distances per group + one scalar compare;
// exact index recovered post-loop by bit-identical recompute of the winning
// group (descending scan -> first occurrence). Publish via per-lane
// atomicMax(~((d2bits<<32)|n)); 32nd-arriving warp finalizes + resets.

#define BATCH 8
#define MM    512
#define NN    8192
#define NSPLIT 4
#define TN    (NN / NSPLIT)      // 2048 points per split-tile
#define WPB   8                  // warps per block
#define PPW   256                // points per warp
#define GPTS  8                  // points per inner group
#define NGROUPS (PPW / GPTS)     // 32 groups per warp
#define NGRP  (BATCH * MM / 32)  // 128 keypoint groups
#define NARRIVE (NSPLIT * WPB)   // 32 warp arrivals per group
#define EPSV  1e-7f

// zero-initialized device state; reset by the finalizing warp each launch
__device__ unsigned long long g_inv[NGRP * 32];   // ~key, max-reduced
__device__ unsigned int       g_cnt[NGRP];        // warp-arrival counters

union f2u  { float2 f; uint64_t u; };
union f4u2 { float4 f; ulonglong2 u; };   // .u.x = (f.x,f.y), .u.y = (f.z,f.w)

__device__ __forceinline__ uint64_t add2(uint64_t a, uint64_t b) {
    uint64_t r; asm("add.rn.f32x2 %0, %1, %2;" : "=l"(r) : "l"(a), "l"(b)); return r;
}
__device__ __forceinline__ uint64_t mul2(uint64_t a, uint64_t b) {
    uint64_t r; asm("mul.rn.f32x2 %0, %1, %2;" : "=l"(r) : "l"(a), "l"(b)); return r;
}
__device__ __forceinline__ uint64_t fma2(uint64_t a, uint64_t b, uint64_t c) {
    uint64_t r; asm("fma.rn.f32x2 %0, %1, %2, %3;" : "=l"(r) : "l"(a), "l"(b), "l"(c)); return r;
}
__device__ __forceinline__ uint64_t pack2(float lo, float hi) {
    uint64_t r; asm("mov.b64 %0, {%1, %2};" : "=l"(r) : "f"(lo), "f"(hi)); return r;
}

// squared distance for a packed point-pair; bit-exact chain (reused in recovery)
__device__ __forceinline__ float2 eval_pair(uint64_t xp, uint64_t yp, uint64_t zp,
                                            uint64_t nkx2, uint64_t nky2, uint64_t nkz2)
{
    const uint64_t dx = add2(xp, nkx2);
    const uint64_t dy = add2(yp, nky2);
    const uint64_t dz = add2(zp, nkz2);
    uint64_t s = mul2(dx, dx);
    s = fma2(dy, dy, s);
    s = fma2(dz, dz, s);
    f2u r; r.u = s;
    return r.f;
}

// Cold path: runs once per group by the last-arriving warp.
__device__ __noinline__ void finalize_group(const float* __restrict__ keypoint,
                                            const float* __restrict__ pc,
                                            const float* __restrict__ sn,
                                            float* __restrict__ out,
                                            int grp, int lane)
{
    const int b = grp >> 4;
    const int m = (grp & 15) * 32 + lane;

    __threadfence();
    const unsigned long long inv = atomicMax(&g_inv[grp * 32 + lane], 0ULL);
    const int bn = (int)((~inv) & 0xFFFFFFFFu);

    const float* kpb = keypoint + (size_t)b * 3 * MM;
    const float kx = kpb[0 * MM + m];
    const float ky = kpb[1 * MM + m];
    const float kz = kpb[2 * MM + m];

    const float* pcb = pc + (size_t)b * 3 * NN;
    const float* snb = sn + (size_t)b * 3 * NN;
    const float px = pcb[0 * NN + bn];
    const float py = pcb[1 * NN + bn];
    const float pz = pcb[2 * NN + bn];
    const float sx = snb[0 * NN + bn];
    const float sy = snb[1 * NN + bn];
    const float sz = snb[2 * NN + bn];

    const float dx = kx - px;
    const float dy = ky - py;
    const float dz = kz - pz;
    const float nrm = sqrtf(dx * dx + dy * dy + dz * dz);
    const float dot = (sx * dx + sy * dy + sz * dz) / (nrm + EPSV);
    out[b * MM + m] = dot * dot;

    // reset for next graph replay (deterministic)
    atomicExch(&g_inv[grp * 32 + lane], 0ULL);
    if (lane == 0) atomicExch(&g_cnt[grp], 0u);
}

__global__ __launch_bounds__(256, 4)
void pos_loss_fused(const float* __restrict__ keypoint,
                    const float* __restrict__ pc,
                    const float* __restrict__ sn,
                    float* __restrict__ out)
{
    __shared__ float4 xs4[TN / 4];   // 8 KB each: SoA tile rows, float4-aligned
    __shared__ float4 ys4[TN / 4];
    __shared__ float4 zs4[TN / 4];

    const int blk  = blockIdx.x;             // 512
    const int grp  = blk >> 2;               // keypoint group 0..127
    const int spl  = blk & 3;                // N split
    const int b    = grp >> 4;
    const int tid  = threadIdx.x;
    const int wid  = tid >> 5;
    const int lane = tid & 31;
    const int m    = (grp & 15) * 32 + lane;

    uint64_t nkx2, nky2, nkz2;
    {
        const float* kpb = keypoint + (size_t)b * 3 * MM;
        const float kx = kpb[0 * MM + m];
        const float ky = kpb[1 * MM + m];
        const float kz = kpb[2 * MM + m];
        nkx2 = pack2(-kx, -kx);
        nky2 = pack2(-ky, -ky);
        nkz2 = pack2(-kz, -kz);
    }

    const float* pcb = pc + (size_t)b * 3 * NN;
    const int n0 = spl * TN;

    // stage tile (L2 hits), float4 copies
    {
        const float4* gx = (const float4*)(pcb + 0 * NN + n0);
        const float4* gy = (const float4*)(pcb + 1 * NN + n0);
        const float4* gz = (const float4*)(pcb + 2 * NN + n0);
        #pragma unroll
        for (int i = tid; i < TN / 4; i += 256) {
            xs4[i] = gx[i];
            ys4[i] = gy[i];
            zs4[i] = gz[i];
        }
    }
    __syncthreads();

    // this warp's slice: 256 points = 64 float4, broadcast reads
    const float4* xw = xs4 + wid * (PPW / 4);
    const float4* yw = ys4 + wid * (PPW / 4);
    const float4* zw = zs4 + wid * (PPW / 4);

    float bestd = 3.4e38f;
    int   bestg = 0;

    #pragma unroll 4
    for (int g = 0; g < NGROUPS; ++g) {      // 8 points per group
        const int q = g * 2;
        f4u2 x0, x1, y0, y1, z0, z1;
        x0.f = xw[q + 0]; x1.f = xw[q + 1];
        y0.f = yw[q + 0]; y1.f = yw[q + 1];
        z0.f = zw[q + 0]; z1.f = zw[q + 1];

        const float2 dA = eval_pair(x0.u.x, y0.u.x, z0.u.x, nkx2, nky2, nkz2);
        const float2 dB = eval_pair(x0.u.y, y0.u.y, z0.u.y, nkx2, nky2, nkz2);
        const float2 dC = eval_pair(x1.u.x, y1.u.x, z1.u.x, nkx2, nky2, nkz2);
        const float2 dD = eval_pair(x1.u.y, y1.u.y, z1.u.y, nkx2, nky2, nkz2);

        // pure FMNMX tree: 7 mins, no predicates
        const float mA = fminf(dA.x, dA.y);
        const float mB = fminf(dB.x, dB.y);
        const float mC = fminf(dC.x, dC.y);
        const float mD = fminf(dD.x, dD.y);
        const float mg = fminf(fminf(mA, mB), fminf(mC, mD));

        // strict < keeps the earliest group on ties (first occurrence)
        if (mg < bestd) { bestd = mg; bestg = g; }
    }

    // index recovery: recompute the winning group (bit-identical chain),
    // descending scan so the LOWEST matching index wins
    int bcode = 0;   // 0..7 within group
    {
        const int q = bestg * 2;
        #pragma unroll
        for (int j = 1; j >= 0; --j) {
            f4u2 xv, yv, zv;
            xv.f = xw[q + j]; yv.f = yw[q + j]; zv.f = zw[q + j];
            const float2 dHi = eval_pair(xv.u.y, yv.u.y, zv.u.y, nkx2, nky2, nkz2);
            const float2 dLo = eval_pair(xv.u.x, yv.u.x, zv.u.x, nkx2, nky2, nkz2);
            if (dHi.y == bestd) bcode = 4 * j + 3;
            if (dHi.x == bestd) bcode = 4 * j + 2;
            if (dLo.y == bestd) bcode = 4 * j + 1;
            if (dLo.x == bestd) bcode = 4 * j + 0;
        }
    }

    // packed key: (bits(d2) << 32) | n — uint64 min == lexicographic (d, n) min
    {
        const int n = n0 + wid * PPW + bestg * GPTS + bcode;
        uint32_t dbits; asm("mov.b32 %0, %1;" : "=r"(dbits) : "f"(bestd));
        const unsigned long long key =
            ((unsigned long long)dbits << 32) | (unsigned)n;
        atomicMax(&g_inv[grp * 32 + lane], ~key);
    }
    __threadfence();

    // warp arrival; 32nd warp for this keypoint-group finalizes
    unsigned int prev = 0;
    if (lane == 0) prev = atomicAdd(&g_cnt[grp], 1u);
    prev = __shfl_sync(0xFFFFFFFFu, prev, 0);

    if (prev == NARRIVE - 1u) {
        finalize_group(keypoint, pc, sn, out, grp, lane);
    }
}

extern "C" void kernel_launch(void* const* d_in, const int* in_sizes, int n_in,
                              void* d_out, int out_size)
{
    const float* keypoint = (const float*)d_in[0]; // 8*3*512
    const float* pc       = (const float*)d_in[1]; // 8*3*8192
    const float* sn       = (const float*)d_in[2]; // 8*3*8192
    float* out            = (float*)d_out;         // 4096

    pos_loss_fused<<<NGRP * NSPLIT, 256>>>(keypoint, pc, sn, out);  // 512 blocks
}